// round 6
// baseline (speedup 1.0000x reference)
#include <cuda_runtime.h>
#include <cstdint>

#define KDIM 16384
#define NB 8
#define NC 256
#define TILE 128
#define KCHUNK 8
#define SPLITS 6
#define NKCLUST 16

typedef unsigned long long u64;
union F2U { float2 f; u64 u; };

// ---------------- scratch (no allocations allowed) ----------------
__device__ float g_part[SPLITS][NB][NC][NC];   // split-K partials (upper tiles only)
__device__ float g_G[NB][NC][NC];              // reduced Gram, mirrored full
__device__ int   g_sel[NB][NKCLUST];
__device__ int   g_selpos[NKCLUST];
__device__ int   g_tassign[NB][NC];
__device__ float g_cent[NKCLUST][3];

__device__ __forceinline__ void fma2(u64 &acc, u64 a, u64 b) {
    asm("fma.rn.f32x2 %0, %1, %2, %0;" : "+l"(acc) : "l"(a), "l"(b));
}

// ---------------- Kernel 1: symmetric split-K Gram (C = A A^T per batch) ----
__global__ void __launch_bounds__(256) gram_kernel(const float* __restrict__ A) {
    int tileId = blockIdx.x;          // 0:(0,0) 1:(0,1) 2:(1,1)
    int s = blockIdx.y;
    int b = blockIdx.z;
    int ti = (tileId == 2) ? 1 : 0;
    int tj = (tileId == 0) ? 0 : 1;
    const float* Ab = A + (size_t)b * NC * KDIM;
    const float* Arow = Ab + (size_t)(ti * TILE) * KDIM;
    const float* Brow = Ab + (size_t)(tj * TILE) * KDIM;

    int kb = ((s * KDIM) / SPLITS) & ~7;
    int ke = (((s + 1) * KDIM) / SPLITS) & ~7;

    __shared__ float2 As2[2][KCHUNK][129];   // {a,a} duplicated
    __shared__ float2 Bs2[2][KCHUNK][65];    // column pairs

    int t  = threadIdx.x;
    int tx = t & 15;
    int ty = t >> 4;
    int r0 = ty * 8;
    int c0h = tx * 4;

    int lr = t >> 1;
    int lk = (t & 1) * 4;

    u64 acc[8][4];
#pragma unroll
    for (int i = 0; i < 8; i++)
#pragma unroll
        for (int jj = 0; jj < 4; jj++) acc[i][jj] = 0ull;

    int nChunks = (ke - kb) / KCHUNK;

    {   // prologue load into buffer 0
        float4 av = *reinterpret_cast<const float4*>(Arow + (size_t)lr * KDIM + kb + lk);
        float4 bv = *reinterpret_cast<const float4*>(Brow + (size_t)lr * KDIM + kb + lk);
        float a4[4] = {av.x, av.y, av.z, av.w};
        float b4[4] = {bv.x, bv.y, bv.z, bv.w};
#pragma unroll
        for (int q = 0; q < 4; q++) {
            As2[0][lk + q][lr] = make_float2(a4[q], a4[q]);
            reinterpret_cast<float*>(&Bs2[0][lk + q][0])[lr] = b4[q];
        }
    }
    __syncthreads();

    int buf = 0;
    for (int ch = 0; ch < nChunks; ch++) {
        float4 av, bv;
        bool more = (ch + 1 < nChunks);
        if (more) {
            int k0 = kb + (ch + 1) * KCHUNK;
            av = *reinterpret_cast<const float4*>(Arow + (size_t)lr * KDIM + k0 + lk);
            bv = *reinterpret_cast<const float4*>(Brow + (size_t)lr * KDIM + k0 + lk);
        }
#pragma unroll
        for (int kk = 0; kk < KCHUNK; kk++) {
            u64 a[8];
#pragma unroll
            for (int i = 0; i < 8; i++) {
                F2U u; u.f = As2[buf][kk][r0 + i]; a[i] = u.u;
            }
            u64 bb[4];
#pragma unroll
            for (int jj = 0; jj < 4; jj++) {
                F2U u; u.f = Bs2[buf][kk][c0h + jj]; bb[jj] = u.u;
            }
#pragma unroll
            for (int i = 0; i < 8; i++)
#pragma unroll
                for (int jj = 0; jj < 4; jj++)
                    fma2(acc[i][jj], a[i], bb[jj]);
        }
        __syncthreads();
        if (more) {
            int nb_ = buf ^ 1;
            float a4[4] = {av.x, av.y, av.z, av.w};
            float b4[4] = {bv.x, bv.y, bv.z, bv.w};
#pragma unroll
            for (int q = 0; q < 4; q++) {
                As2[nb_][lk + q][lr] = make_float2(a4[q], a4[q]);
                reinterpret_cast<float*>(&Bs2[nb_][lk + q][0])[lr] = b4[q];
            }
        }
        __syncthreads();
        buf ^= 1;
    }

    int grow = ti * TILE + r0;
    int gcol = tj * TILE + c0h * 2;
#pragma unroll
    for (int i = 0; i < 8; i++) {
        float* dst = &g_part[s][b][grow + i][gcol];
#pragma unroll
        for (int jj = 0; jj < 4; jj++) {
            F2U u; u.u = acc[i][jj];
            dst[2 * jj + 0] = u.f.x;
            dst[2 * jj + 1] = u.f.y;
        }
    }
}

// ---------------- Kernel 2: deterministic split reduction + mirror ---------
__global__ void __launch_bounds__(256) reduce_kernel() {
    int gid = blockIdx.x * 256 + threadIdx.x;
    int b  = gid >> 16;
    int ij = gid & 65535;
    int i  = ij >> 8;
    int j  = ij & 255;
    int si = i, sj = j;
    if (i >= 128 && j < 128) { si = j; sj = i; }
    float acc = 0.0f;
#pragma unroll
    for (int s = 0; s < SPLITS; s++) acc += g_part[s][b][si][sj];
    g_G[b][i][j] = acc;
}

// ---------------- Kernel 3: farthest point sampling (pos + 8 feature sets) -
__global__ void __launch_bounds__(256) fps_kernel(const float* __restrict__ pos) {
    int j = threadIdx.x;
    int mode = blockIdx.x;   // 0 = positions(batch 0), 1..8 = feature batch mode-1
    __shared__ double sdv[256];
    __shared__ int    sidx[256];
    __shared__ float  spx[256], spy[256], spz[256], snrm[256];
    __shared__ int    ssel[NKCLUST];

    const float* Gb = nullptr;
    if (mode == 0) {
        spx[j] = pos[j * 3 + 0];
        spy[j] = pos[j * 3 + 1];
        spz[j] = pos[j * 3 + 2];
    } else {
        Gb = &g_G[mode - 1][0][0];
    }
    __syncthreads();
    if (mode == 0)
        snrm[j] = spx[j] * spx[j] + spy[j] * spy[j] + spz[j] * spz[j];
    else
        snrm[j] = Gb[j * 256 + j];
    __syncthreads();

    auto dist = [&](int i) -> float {
        float d2;
        if (mode == 0) {
            float dot = spx[i] * spx[j] + spy[i] * spy[j] + spz[i] * spz[j];
            d2 = snrm[i] + snrm[j] - 2.0f * dot;
        } else {
            d2 = snrm[i] + snrm[j] - 2.0f * Gb[i * 256 + j];
        }
        return sqrtf(fmaxf(d2, 0.0f));
    };

    // start = argmax of row sums
    double rs = 0.0;
    for (int i = 0; i < 256; i++) rs += (double)dist(i);
    sdv[j] = rs; sidx[j] = j;
    __syncthreads();
    for (int off = 128; off > 0; off >>= 1) {
        if (j < off) {
            double v2 = sdv[j + off]; int i2 = sidx[j + off];
            if (v2 > sdv[j] || (v2 == sdv[j] && i2 < sidx[j])) { sdv[j] = v2; sidx[j] = i2; }
        }
        __syncthreads();
    }
    int cur = sidx[0];
    __syncthreads();
    if (j == 0) ssel[0] = cur;
    float mind = dist(cur);

    for (int it = 1; it < NKCLUST; it++) {
        sdv[j] = (double)mind; sidx[j] = j;
        __syncthreads();
        for (int off = 128; off > 0; off >>= 1) {
            if (j < off) {
                double v2 = sdv[j + off]; int i2 = sidx[j + off];
                if (v2 > sdv[j] || (v2 == sdv[j] && i2 < sidx[j])) { sdv[j] = v2; sidx[j] = i2; }
            }
            __syncthreads();
        }
        cur = sidx[0];
        __syncthreads();
        if (j == 0) ssel[it] = cur;
        mind = fminf(mind, dist(cur));
    }
    __syncthreads();
    if (j < NKCLUST) {
        if (mode == 0) g_selpos[j] = ssel[j];
        else           g_sel[mode - 1][j] = ssel[j];
    }
}

// ---------------- Kernel 4: temp assignment (argmin to per-batch centers) --
__global__ void __launch_bounds__(256) assign_kernel(const float* __restrict__ pos) {
    int b = blockIdx.x;
    int c = threadIdx.x;
    __shared__ float cx[NKCLUST], cy[NKCLUST], cz[NKCLUST], cn[NKCLUST];
    if (c < NKCLUST) {
        int si = g_sel[b][c];
        float x = pos[(b * 256 + si) * 3 + 0];
        float y = pos[(b * 256 + si) * 3 + 1];
        float z = pos[(b * 256 + si) * 3 + 2];
        cx[c] = x; cy[c] = y; cz[c] = z; cn[c] = x * x + y * y + z * z;
    }
    __syncthreads();
    float px = pos[(b * 256 + c) * 3 + 0];
    float py = pos[(b * 256 + c) * 3 + 1];
    float pz = pos[(b * 256 + c) * 3 + 2];
    float pn = px * px + py * py + pz * pz;
    float best = 1e30f; int bi = 0;
    for (int k = 0; k < NKCLUST; k++) {
        float d2 = pn + cn[k] - 2.0f * (px * cx[k] + py * cy[k] + pz * cz[k]);
        float d = sqrtf(fmaxf(d2, 0.0f));
        if (d < best) { best = d; bi = k; }
    }
    g_tassign[b][c] = bi;
}

// ---------------- Kernel 5: segment means, matching, center update ---------
__global__ void update_kernel(const float* __restrict__ pos) {
    int k = threadIdx.x;
    __shared__ float ax[NKCLUST], ay[NKCLUST], az[NKCLUST], an[NKCLUST];
    if (k < NKCLUST) {
        float sx = 0.f, sy = 0.f, sz = 0.f, cnt = 0.f;
        const int* ta = &g_tassign[0][0];
        for (int f = 0; f < NB * NC; f++) {
            if (ta[f] == k) {
                sx += pos[f * 3 + 0];
                sy += pos[f * 3 + 1];
                sz += pos[f * 3 + 2];
                cnt += 1.0f;
            }
        }
        if (cnt > 0.f) {
            float dn = fmaxf(cnt, 1.0f);
            ax[k] = sx / dn; ay[k] = sy / dn; az[k] = sz / dn;
        } else {
            ax[k] = 0.f; ay[k] = 0.f; az[k] = 0.f;
        }
        an[k] = ax[k] * ax[k] + ay[k] * ay[k] + az[k] * az[k];
    }
    __syncthreads();
    if (k < NKCLUST) {
        int si = g_selpos[k];
        float cx = pos[si * 3 + 0];
        float cy = pos[si * 3 + 1];
        float cz = pos[si * 3 + 2];
        float cnrm = cx * cx + cy * cy + cz * cz;
        float best = 1e30f; int bm = 0;
        for (int m = 0; m < NKCLUST; m++) {
            float d2 = cnrm + an[m] - 2.0f * (cx * ax[m] + cy * ay[m] + cz * az[m]);
            float d = sqrtf(fmaxf(d2, 0.0f));
            if (d < best) { best = d; bm = m; }
        }
        g_cent[k][0] = 0.8f * cx + 0.2f * ax[bm];
        g_cent[k][1] = 0.8f * cy + 0.2f * ay[bm];
        g_cent[k][2] = 0.8f * cz + 0.2f * az[bm];
    }
}

// ---------------- Kernel 6: stable argsort + greedy capacity assign --------
// OUTPUT IS float32: the harness's __output__ dtype is float (int labels read
// as float bit-patterns explain the exact rel_err = 1.0 of previous rounds).
__global__ void __launch_bounds__(256) final_kernel(const float* __restrict__ pos,
                                                    float* __restrict__ out) {
    int r = threadIdx.x;
    __shared__ float cx[NKCLUST], cy[NKCLUST], cz[NKCLUST], cn[NKCLUST];
    __shared__ unsigned char sord[256][NKCLUST];
    if (r < NKCLUST) {
        cx[r] = g_cent[r][0]; cy[r] = g_cent[r][1]; cz[r] = g_cent[r][2];
        cn[r] = cx[r] * cx[r] + cy[r] * cy[r] + cz[r] * cz[r];
    }
    __syncthreads();
    float px = pos[r * 3 + 0], py = pos[r * 3 + 1], pz = pos[r * 3 + 2];
    float pn = px * px + py * py + pz * pz;
    float d[NKCLUST];
    int ord[NKCLUST];
    for (int k = 0; k < NKCLUST; k++) {
        float d2 = pn + cn[k] - 2.0f * (px * cx[k] + py * cy[k] + pz * cz[k]);
        d[k] = sqrtf(fmaxf(d2, 0.0f));
        ord[k] = k;
    }
    // stable insertion sort ascending (ties keep lower index, like jnp.argsort)
    for (int a = 1; a < NKCLUST; a++) {
        int key = ord[a]; float kd = d[key];
        int bq = a - 1;
        while (bq >= 0 && d[ord[bq]] > kd) { ord[bq + 1] = ord[bq]; bq--; }
        ord[bq + 1] = key;
    }
    for (int k = 0; k < NKCLUST; k++) sord[r][k] = (unsigned char)ord[k];
    __syncthreads();
    if (r == 0) {
        int counts[NKCLUST];
        for (int k = 0; k < NKCLUST; k++) counts[k] = 0;
        for (int rr = 0; rr < 256; rr++) {
            int chosen = sord[rr][0];
            for (int k = 0; k < NKCLUST; k++) {
                int cid = sord[rr][k];
                if (counts[cid] < 16) { chosen = cid; break; }
            }
            counts[chosen]++;
            out[rr] = (float)chosen;
        }
    }
}

// ---------------- launch ----------------
extern "C" void kernel_launch(void* const* d_in, const int* in_sizes, int n_in,
                              void* d_out, int out_size) {
    // Resolve inputs by element count; fall back to positional order.
    const float* features = nullptr;
    const float* pos = nullptr;
    for (int i = 0; i < n_in; i++) {
        if (in_sizes[i] == NB * NC * KDIM)      features = (const float*)d_in[i];
        else if (in_sizes[i] == NB * NC * 3)    pos      = (const float*)d_in[i];
    }
    if (!features) features = (const float*)d_in[0];
    if (!pos)      pos      = (const float*)d_in[1];
    float* out = (float*)d_out;

    dim3 g1(3, SPLITS, NB);
    gram_kernel<<<g1, 256>>>(features);
    reduce_kernel<<<(NB * NC * NC) / 256, 256>>>();
    fps_kernel<<<9, 256>>>(pos);
    assign_kernel<<<NB, 256>>>(pos);
    update_kernel<<<1, 32>>>(pos);
    final_kernel<<<1, 256>>>(pos, out);
}

// round 8
// speedup vs baseline: 1.5279x; 1.5279x over previous
#include <cuda_runtime.h>
#include <cuda_bf16.h>
#include <cstdint>

#define KDIM 16384
#define NB 8
#define NC 256
#define NKCLUST 16
#define SPLITS 6
#define KC 64
#define TILEB 16384            // one 128x64 bf16 tile in smem
#define SM_TOTAL (8 * TILEB)   // 2 buffers x {Ahi,Alo,Bhi,Blo}

// ---------------- scratch ----------------
__device__ float g_part[SPLITS][NB][NC][NC];
__device__ float g_G[NB][NC][NC];
__device__ int   g_sel[NB][NKCLUST];
__device__ int   g_selpos[NKCLUST];
__device__ int   g_tassign[NB][NC];
__device__ float g_cent[NKCLUST][3];

__device__ __forceinline__ uint32_t smem_u32(const void* p) {
    uint32_t a;
    asm("{ .reg .u64 t; cvta.to.shared.u64 t, %1; cvt.u32.u64 %0, t; }" : "=r"(a) : "l"(p));
    return a;
}
__device__ __forceinline__ uint32_t sw128(uint32_t off) { return off ^ ((off >> 3) & 0x70); }

#define LDSM4(r, addr) \
    asm volatile("ldmatrix.sync.aligned.m8n8.x4.shared.b16 {%0,%1,%2,%3}, [%4];" \
                 : "=r"((r)[0]), "=r"((r)[1]), "=r"((r)[2]), "=r"((r)[3]) : "r"(addr))

__device__ __forceinline__ void mma16816(float* c, const uint32_t* a, const uint32_t* b) {
    asm volatile("mma.sync.aligned.m16n8k16.row.col.f32.bf16.bf16.f32 "
                 "{%0,%1,%2,%3}, {%4,%5,%6,%7}, {%8,%9}, {%0,%1,%2,%3};"
                 : "+f"(c[0]), "+f"(c[1]), "+f"(c[2]), "+f"(c[3])
                 : "r"(a[0]), "r"(a[1]), "r"(a[2]), "r"(a[3]), "r"(b[0]), "r"(b[1]));
}

__device__ __forceinline__ uint32_t packbf(float x, float y) {
    __nv_bfloat16 h0 = __float2bfloat16(x), h1 = __float2bfloat16(y);
    return (uint32_t)__bfloat16_as_ushort(h0) | ((uint32_t)__bfloat16_as_ushort(h1) << 16);
}

// convert one float4 (4 fp32) -> hi/lo bf16 pairs, store 8B each to swizzled smem
__device__ __forceinline__ void cvt_store(char* hiT, char* loT, int row, int col, float4 v) {
    float hx = __bfloat162float(__float2bfloat16(v.x));
    float hy = __bfloat162float(__float2bfloat16(v.y));
    float hz = __bfloat162float(__float2bfloat16(v.z));
    float hw = __bfloat162float(__float2bfloat16(v.w));
    uint2 hp, lp;
    hp.x = packbf(v.x, v.y);      hp.y = packbf(v.z, v.w);
    lp.x = packbf(v.x - hx, v.y - hy);
    lp.y = packbf(v.z - hz, v.w - hw);
    uint32_t off = sw128((uint32_t)(row * 128 + col * 2));
    *reinterpret_cast<uint2*>(hiT + off) = hp;
    *reinterpret_cast<uint2*>(loT + off) = lp;
}

// ---------------- Kernel 1: mma.sync bf16-split Gram ----------------
// grid (3 tiles, SPLITS, NB), block 256
__global__ void __launch_bounds__(256, 1) gram_mma(const float* __restrict__ A) {
    extern __shared__ char smem[];
    uint32_t smb = smem_u32(smem);
    int tileId = blockIdx.x, s = blockIdx.y, b = blockIdx.z;
    int ti = (tileId == 2) ? 1 : 0;
    int tj = (tileId == 0) ? 0 : 1;
    const float* Ab = A + (size_t)b * NC * KDIM;
    const float* Arow = Ab + (size_t)(ti * 128) * KDIM;
    const float* Brow = Ab + (size_t)(tj * 128) * KDIM;

    int kb = ((s * KDIM) / SPLITS) & ~63;
    int ke = (((s + 1) * KDIM) / SPLITS) & ~63;
    if (s == SPLITS - 1) ke = KDIM;
    int n = (ke - kb) / KC;

    int t = threadIdx.x, l = t & 31, wid = t >> 5;
    int wr = wid >> 2, wc = wid & 3;          // warp tile: 64x32 at (wr*64, wc*32)
    int crow = t >> 1, ccb = (t & 1) * 32;    // conversion: 2 threads/row, 32 floats each

    float acc[4][4][4];
#pragma unroll
    for (int f = 0; f < 4; f++)
#pragma unroll
        for (int g = 0; g < 4; g++)
#pragma unroll
            for (int q = 0; q < 4; q++) acc[f][g][q] = 0.0f;

    // ldmatrix per-lane row offsets (bytes, without kk term)
    int mL = l & 15;
    int kaA = ((l >> 4) & 1) * 16;
    int nL = (l & 7) + ((l >> 4) & 1) * 8;
    int kaB = ((l >> 3) & 1) * 16;
    uint32_t arow[4], brow[2];
#pragma unroll
    for (int f = 0; f < 4; f++) arow[f] = (uint32_t)((wr * 64 + f * 16 + mL) * 128 + kaA);
#pragma unroll
    for (int g2 = 0; g2 < 2; g2++) brow[g2] = (uint32_t)((wc * 32 + g2 * 16 + nL) * 128 + kaB);

    // prologue: convert chunk 0 into buffer 0
    {
        char* ahiT = smem + 0 * TILEB; char* aloT = smem + 1 * TILEB;
        char* bhiT = smem + 2 * TILEB; char* bloT = smem + 3 * TILEB;
        const float* sa = Arow + (size_t)crow * KDIM + kb + ccb;
        const float* sb = Brow + (size_t)crow * KDIM + kb + ccb;
#pragma unroll
        for (int i = 0; i < 8; i++) {
            cvt_store(ahiT, aloT, crow, ccb + i * 4, *reinterpret_cast<const float4*>(sa + i * 4));
            cvt_store(bhiT, bloT, crow, ccb + i * 4, *reinterpret_cast<const float4*>(sb + i * 4));
        }
    }
    __syncthreads();

    for (int ch = 0; ch < n; ch++) {
        int buf = ch & 1;
        bool more = (ch + 1 < n);
        float4 va[8], vb[8];
        if (more) {
            int k0 = kb + (ch + 1) * KC + ccb;
            const float* sa = Arow + (size_t)crow * KDIM + k0;
            const float* sb = Brow + (size_t)crow * KDIM + k0;
#pragma unroll
            for (int i = 0; i < 8; i++) va[i] = *reinterpret_cast<const float4*>(sa + i * 4);
#pragma unroll
            for (int i = 0; i < 8; i++) vb[i] = *reinterpret_cast<const float4*>(sb + i * 4);
        }

        uint32_t base = smb + (uint32_t)buf * 4 * TILEB;
        uint32_t ahiB = base, aloB = base + TILEB, bhiB = base + 2 * TILEB, bloB = base + 3 * TILEB;
#pragma unroll
        for (int kk = 0; kk < 4; kk++) {
            uint32_t ah[4][4], al[4][4], bh[2][4], bl[2][4];
#pragma unroll
            for (int f = 0; f < 4; f++) {
                uint32_t o = sw128(arow[f] + kk * 32);
                LDSM4(ah[f], ahiB + o);
                LDSM4(al[f], aloB + o);
            }
#pragma unroll
            for (int g2 = 0; g2 < 2; g2++) {
                uint32_t o = sw128(brow[g2] + kk * 32);
                LDSM4(bh[g2], bhiB + o);
                LDSM4(bl[g2], bloB + o);
            }
#pragma unroll
            for (int f = 0; f < 4; f++)
#pragma unroll
                for (int g = 0; g < 4; g++) {
                    const uint32_t* Bh = &bh[g >> 1][(g & 1) * 2];
                    const uint32_t* Bl = &bl[g >> 1][(g & 1) * 2];
                    mma16816(acc[f][g], ah[f], Bh);
                    mma16816(acc[f][g], ah[f], Bl);
                    mma16816(acc[f][g], al[f], Bh);
                }
        }

        if (more) {
            int nb_ = buf ^ 1;
            char* ahiT = smem + (4 * nb_ + 0) * TILEB; char* aloT = smem + (4 * nb_ + 1) * TILEB;
            char* bhiT = smem + (4 * nb_ + 2) * TILEB; char* bloT = smem + (4 * nb_ + 3) * TILEB;
#pragma unroll
            for (int i = 0; i < 8; i++) cvt_store(ahiT, aloT, crow, ccb + i * 4, va[i]);
#pragma unroll
            for (int i = 0; i < 8; i++) cvt_store(bhiT, bloT, crow, ccb + i * 4, vb[i]);
        }
        __syncthreads();
    }

    // epilogue: c-frag layout m16n8: (c0,c1)@(row l/4, col 2(l%4)), (c2,c3)@(row+8)
#pragma unroll
    for (int f = 0; f < 4; f++)
#pragma unroll
        for (int g = 0; g < 4; g++) {
            int m = wr * 64 + f * 16 + (l >> 2);
            int nn = wc * 32 + g * 8 + (l & 3) * 2;
            int gm = ti * 128 + m, gn = tj * 128 + nn;
            float2 v0 = make_float2(acc[f][g][0], acc[f][g][1]);
            float2 v1 = make_float2(acc[f][g][2], acc[f][g][3]);
            *reinterpret_cast<float2*>(&g_part[s][b][gm][gn]) = v0;
            *reinterpret_cast<float2*>(&g_part[s][b][gm + 8][gn]) = v1;
        }
}

// ---------------- Kernel 2: deterministic split reduction + mirror ---------
__global__ void __launch_bounds__(256) reduce_kernel() {
    int gid = blockIdx.x * 256 + threadIdx.x;
    int b  = gid >> 16;
    int ij = gid & 65535;
    int i  = ij >> 8;
    int j  = ij & 255;
    int si = i, sj = j;
    if (i >= 128 && j < 128) { si = j; sj = i; }
    float acc = 0.0f;
#pragma unroll
    for (int s = 0; s < SPLITS; s++) acc += g_part[s][b][si][sj];
    g_G[b][i][j] = acc;
}

// ---------------- Kernel 3: farthest point sampling ----------------
__global__ void __launch_bounds__(256) fps_kernel(const float* __restrict__ pos) {
    int j = threadIdx.x;
    int mode = blockIdx.x;
    __shared__ double sdv[256];
    __shared__ int    sidx[256];
    __shared__ float  spx[256], spy[256], spz[256], snrm[256];
    __shared__ int    ssel[NKCLUST];

    const float* Gb = nullptr;
    if (mode == 0) {
        spx[j] = pos[j * 3 + 0]; spy[j] = pos[j * 3 + 1]; spz[j] = pos[j * 3 + 2];
    } else {
        Gb = &g_G[mode - 1][0][0];
    }
    __syncthreads();
    if (mode == 0) snrm[j] = spx[j] * spx[j] + spy[j] * spy[j] + spz[j] * spz[j];
    else           snrm[j] = Gb[j * 256 + j];
    __syncthreads();

    auto dist = [&](int i) -> float {
        float d2;
        if (mode == 0) {
            float dot = spx[i] * spx[j] + spy[i] * spy[j] + spz[i] * spz[j];
            d2 = snrm[i] + snrm[j] - 2.0f * dot;
        } else {
            d2 = snrm[i] + snrm[j] - 2.0f * Gb[i * 256 + j];
        }
        return sqrtf(fmaxf(d2, 0.0f));
    };

    double rs = 0.0;
    for (int i = 0; i < 256; i++) rs += (double)dist(i);
    sdv[j] = rs; sidx[j] = j;
    __syncthreads();
    for (int off = 128; off > 0; off >>= 1) {
        if (j < off) {
            double v2 = sdv[j + off]; int i2 = sidx[j + off];
            if (v2 > sdv[j] || (v2 == sdv[j] && i2 < sidx[j])) { sdv[j] = v2; sidx[j] = i2; }
        }
        __syncthreads();
    }
    int cur = sidx[0];
    __syncthreads();
    if (j == 0) ssel[0] = cur;
    float mind = dist(cur);

    for (int it = 1; it < NKCLUST; it++) {
        sdv[j] = (double)mind; sidx[j] = j;
        __syncthreads();
        for (int off = 128; off > 0; off >>= 1) {
            if (j < off) {
                double v2 = sdv[j + off]; int i2 = sidx[j + off];
                if (v2 > sdv[j] || (v2 == sdv[j] && i2 < sidx[j])) { sdv[j] = v2; sidx[j] = i2; }
            }
            __syncthreads();
        }
        cur = sidx[0];
        __syncthreads();
        if (j == 0) ssel[it] = cur;
        mind = fminf(mind, dist(cur));
    }
    __syncthreads();
    if (j < NKCLUST) {
        if (mode == 0) g_selpos[j] = ssel[j];
        else           g_sel[mode - 1][j] = ssel[j];
    }
}

// ---------------- Kernel 4: temp assignment ----------------
__global__ void __launch_bounds__(256) assign_kernel(const float* __restrict__ pos) {
    int b = blockIdx.x;
    int c = threadIdx.x;
    __shared__ float cx[NKCLUST], cy[NKCLUST], cz[NKCLUST], cn[NKCLUST];
    if (c < NKCLUST) {
        int si = g_sel[b][c];
        float x = pos[(b * 256 + si) * 3 + 0];
        float y = pos[(b * 256 + si) * 3 + 1];
        float z = pos[(b * 256 + si) * 3 + 2];
        cx[c] = x; cy[c] = y; cz[c] = z; cn[c] = x * x + y * y + z * z;
    }
    __syncthreads();
    float px = pos[(b * 256 + c) * 3 + 0];
    float py = pos[(b * 256 + c) * 3 + 1];
    float pz = pos[(b * 256 + c) * 3 + 2];
    float pn = px * px + py * py + pz * pz;
    float best = 1e30f; int bi = 0;
    for (int k = 0; k < NKCLUST; k++) {
        float d2 = pn + cn[k] - 2.0f * (px * cx[k] + py * cy[k] + pz * cz[k]);
        float d = sqrtf(fmaxf(d2, 0.0f));
        if (d < best) { best = d; bi = k; }
    }
    g_tassign[b][c] = bi;
}

// ---------------- Kernel 5: segment means + matching + update ----------------
__global__ void update_kernel(const float* __restrict__ pos) {
    int k = threadIdx.x;
    __shared__ float ax[NKCLUST], ay[NKCLUST], az[NKCLUST], an[NKCLUST];
    if (k < NKCLUST) {
        float sx = 0.f, sy = 0.f, sz = 0.f, cnt = 0.f;
        const int* ta = &g_tassign[0][0];
        for (int f = 0; f < NB * NC; f++) {
            if (ta[f] == k) {
                sx += pos[f * 3 + 0]; sy += pos[f * 3 + 1]; sz += pos[f * 3 + 2];
                cnt += 1.0f;
            }
        }
        if (cnt > 0.f) {
            float dn = fmaxf(cnt, 1.0f);
            ax[k] = sx / dn; ay[k] = sy / dn; az[k] = sz / dn;
        } else { ax[k] = 0.f; ay[k] = 0.f; az[k] = 0.f; }
        an[k] = ax[k] * ax[k] + ay[k] * ay[k] + az[k] * az[k];
    }
    __syncthreads();
    if (k < NKCLUST) {
        int si = g_selpos[k];
        float cx = pos[si * 3 + 0], cy = pos[si * 3 + 1], cz = pos[si * 3 + 2];
        float cnrm = cx * cx + cy * cy + cz * cz;
        float best = 1e30f; int bm = 0;
        for (int m = 0; m < NKCLUST; m++) {
            float d2 = cnrm + an[m] - 2.0f * (cx * ax[m] + cy * ay[m] + cz * az[m]);
            float d = sqrtf(fmaxf(d2, 0.0f));
            if (d < best) { best = d; bm = m; }
        }
        g_cent[k][0] = 0.8f * cx + 0.2f * ax[bm];
        g_cent[k][1] = 0.8f * cy + 0.2f * ay[bm];
        g_cent[k][2] = 0.8f * cz + 0.2f * az[bm];
    }
}

// ---------------- Kernel 6: stable argsort + greedy capacity assign ---------
__global__ void __launch_bounds__(256) final_kernel(const float* __restrict__ pos,
                                                    float* __restrict__ out) {
    int r = threadIdx.x;
    __shared__ float cx[NKCLUST], cy[NKCLUST], cz[NKCLUST], cn[NKCLUST];
    __shared__ unsigned char sord[256][NKCLUST];
    if (r < NKCLUST) {
        cx[r] = g_cent[r][0]; cy[r] = g_cent[r][1]; cz[r] = g_cent[r][2];
        cn[r] = cx[r] * cx[r] + cy[r] * cy[r] + cz[r] * cz[r];
    }
    __syncthreads();
    float px = pos[r * 3 + 0], py = pos[r * 3 + 1], pz = pos[r * 3 + 2];
    float pn = px * px + py * py + pz * pz;
    float d[NKCLUST];
    int ord[NKCLUST];
    for (int k = 0; k < NKCLUST; k++) {
        float d2 = pn + cn[k] - 2.0f * (px * cx[k] + py * cy[k] + pz * cz[k]);
        d[k] = sqrtf(fmaxf(d2, 0.0f));
        ord[k] = k;
    }
    for (int a = 1; a < NKCLUST; a++) {
        int key = ord[a]; float kd = d[key];
        int bq = a - 1;
        while (bq >= 0 && d[ord[bq]] > kd) { ord[bq + 1] = ord[bq]; bq--; }
        ord[bq + 1] = key;
    }
    for (int k = 0; k < NKCLUST; k++) sord[r][k] = (unsigned char)ord[k];
    __syncthreads();
    if (r == 0) {
        int counts[NKCLUST];
        for (int k = 0; k < NKCLUST; k++) counts[k] = 0;
        for (int rr = 0; rr < 256; rr++) {
            int chosen = sord[rr][0];
            for (int k = 0; k < NKCLUST; k++) {
                int cid = sord[rr][k];
                if (counts[cid] < 16) { chosen = cid; break; }
            }
            counts[chosen]++;
            out[rr] = (float)chosen;
        }
    }
}

// ---------------- launch ----------------
extern "C" void kernel_launch(void* const* d_in, const int* in_sizes, int n_in,
                              void* d_out, int out_size) {
    const float* features = nullptr;
    const float* pos = nullptr;
    for (int i = 0; i < n_in; i++) {
        if (in_sizes[i] == NB * NC * KDIM)   features = (const float*)d_in[i];
        else if (in_sizes[i] == NB * NC * 3) pos      = (const float*)d_in[i];
    }
    if (!features) features = (const float*)d_in[0];
    if (!pos)      pos      = (const float*)d_in[1];
    float* out = (float*)d_out;

    cudaFuncSetAttribute(gram_mma, cudaFuncAttributeMaxDynamicSharedMemorySize, SM_TOTAL);

    dim3 g1(3, SPLITS, NB);
    gram_mma<<<g1, 256, SM_TOTAL>>>(features);
    reduce_kernel<<<(NB * NC * NC) / 256, 256>>>();
    fps_kernel<<<9, 256>>>(pos);
    assign_kernel<<<NB, 256>>>(pos);
    update_kernel<<<1, 32>>>(pos);
    final_kernel<<<1, 256>>>(pos, out);
}

// round 10
// speedup vs baseline: 1.6859x; 1.1034x over previous
#include <cuda_runtime.h>
#include <cuda_bf16.h>
#include <cstdint>

#define KDIM 16384
#define NB 8
#define NC 256
#define NKCLUST 16
#define SPLITS 6
#define KC 64
#define TILEB 16384              // one 128x64 bf16 tile (128B rows)
#define BUFB  (4 * TILEB)        // Ahi,Alo,Bhi,Blo per stage
#define NSTAGE 3
#define SM_TOTAL (NSTAGE * BUFB) // 192KB dynamic smem

// ---------------- scratch ----------------
__device__ __nv_bfloat16 g_hi[NB][NC][KDIM];   // 67MB
__device__ __nv_bfloat16 g_lo[NB][NC][KDIM];   // 67MB
__device__ float g_part[SPLITS][NB][NC][NC];
__device__ float g_G[NB][NC][NC];
__device__ int   g_sel[NB][NKCLUST];
__device__ int   g_selpos[NKCLUST];
__device__ int   g_tassign[NB][NC];
__device__ float g_cent[NKCLUST][3];

__device__ __forceinline__ uint32_t smem_u32(const void* p) {
    uint32_t a;
    asm("{ .reg .u64 t; cvta.to.shared.u64 t, %1; cvt.u32.u64 %0, t; }" : "=r"(a) : "l"(p));
    return a;
}
__device__ __forceinline__ uint32_t sw128(uint32_t off) { return off ^ ((off >> 3) & 0x70); }

#define CP_ASYNC16(dst, src) \
    asm volatile("cp.async.cg.shared.global [%0], [%1], 16;" :: "r"(dst), "l"(src))
#define CP_COMMIT() asm volatile("cp.async.commit_group;" ::: "memory")
#define CP_WAIT(N)  asm volatile("cp.async.wait_group %0;" :: "n"(N) : "memory")

#define LDSM4(r, addr) \
    asm volatile("ldmatrix.sync.aligned.m8n8.x4.shared.b16 {%0,%1,%2,%3}, [%4];" \
                 : "=r"((r)[0]), "=r"((r)[1]), "=r"((r)[2]), "=r"((r)[3]) : "r"(addr))

__device__ __forceinline__ void mma16816(float* c, const uint32_t* a, const uint32_t* b) {
    asm volatile("mma.sync.aligned.m16n8k16.row.col.f32.bf16.bf16.f32 "
                 "{%0,%1,%2,%3}, {%4,%5,%6,%7}, {%8,%9}, {%0,%1,%2,%3};"
                 : "+f"(c[0]), "+f"(c[1]), "+f"(c[2]), "+f"(c[3])
                 : "r"(a[0]), "r"(a[1]), "r"(a[2]), "r"(a[3]), "r"(b[0]), "r"(b[1]));
}

// ---------------- Kernel D: dummy (ncu slot alignment) ----------------
__global__ void dummy_kernel() {}

// ---------------- Kernel 0: fp32 -> bf16 hi/lo split (bandwidth pass) ------
__global__ void __launch_bounds__(256) convert_kernel(const float* __restrict__ A) {
    size_t gid = (size_t)blockIdx.x * 256 + threadIdx.x;
    size_t base = gid * 8;
    float4 v0 = *reinterpret_cast<const float4*>(A + base);
    float4 v1 = *reinterpret_cast<const float4*>(A + base + 4);
    __nv_bfloat162 h[4];
    h[0] = __float22bfloat162_rn(make_float2(v0.x, v0.y));
    h[1] = __float22bfloat162_rn(make_float2(v0.z, v0.w));
    h[2] = __float22bfloat162_rn(make_float2(v1.x, v1.y));
    h[3] = __float22bfloat162_rn(make_float2(v1.z, v1.w));
    float2 f0 = __bfloat1622float2(h[0]), f1 = __bfloat1622float2(h[1]);
    float2 f2 = __bfloat1622float2(h[2]), f3 = __bfloat1622float2(h[3]);
    __nv_bfloat162 l[4];
    l[0] = __float22bfloat162_rn(make_float2(v0.x - f0.x, v0.y - f0.y));
    l[1] = __float22bfloat162_rn(make_float2(v0.z - f1.x, v0.w - f1.y));
    l[2] = __float22bfloat162_rn(make_float2(v1.x - f2.x, v1.y - f2.y));
    l[3] = __float22bfloat162_rn(make_float2(v1.z - f3.x, v1.w - f3.y));
    *reinterpret_cast<uint4*>(&g_hi[0][0][0] + base) = *reinterpret_cast<uint4*>(h);
    *reinterpret_cast<uint4*>(&g_lo[0][0][0] + base) = *reinterpret_cast<uint4*>(l);
}

// ---------------- Kernel 1: bf16 mma.sync Gram, cp.async 3-stage -----------
// grid (3 tiles, SPLITS, NB), block 256
__global__ void __launch_bounds__(256, 1) gram_mma(int unused) {
    extern __shared__ char smem[];
    uint32_t smb = smem_u32(smem);
    int tileId = blockIdx.x, s = blockIdx.y, b = blockIdx.z;
    int ti = (tileId == 2) ? 1 : 0;
    int tj = (tileId == 0) ? 0 : 1;
    bool diag = (ti == tj);

    const __nv_bfloat16* AhiR = &g_hi[b][ti * 128][0];
    const __nv_bfloat16* AloR = &g_lo[b][ti * 128][0];
    const __nv_bfloat16* BhiR = &g_hi[b][tj * 128][0];
    const __nv_bfloat16* BloR = &g_lo[b][tj * 128][0];

    int kb = ((s * KDIM) / SPLITS) & ~63;
    int ke = (((s + 1) * KDIM) / SPLITS) & ~63;
    if (s == SPLITS - 1) ke = KDIM;
    int n = (ke - kb) / KC;

    int t = threadIdx.x, l = t & 31, wid = t >> 5;
    int wr = wid >> 2, wc = wid & 3;

    int lrow = t >> 1;                 // 0..127
    int lseg = (t & 1) * 4;            // 16B seg base within row (8 segs/row)

    float acc[4][4][4];
#pragma unroll
    for (int f = 0; f < 4; f++)
#pragma unroll
        for (int g = 0; g < 4; g++)
#pragma unroll
            for (int q = 0; q < 4; q++) acc[f][g][q] = 0.0f;

    int mL = l & 15;
    int kaA = ((l >> 4) & 1) * 16;
    int nL = (l & 7) + ((l >> 4) & 1) * 8;
    int kaB = ((l >> 3) & 1) * 16;
    uint32_t arow[4], brow[2];
#pragma unroll
    for (int f = 0; f < 4; f++) arow[f] = (uint32_t)((wr * 64 + f * 16 + mL) * 128 + kaA);
#pragma unroll
    for (int g2 = 0; g2 < 2; g2++) brow[g2] = (uint32_t)((wc * 32 + g2 * 16 + nL) * 128 + kaB);

    auto load_chunk = [&](int c) {
        if (c < n) {
            int k0 = kb + c * KC;
            uint32_t base = smb + (uint32_t)(c % NSTAGE) * BUFB;
            const __nv_bfloat16* srcAh = AhiR + (size_t)lrow * KDIM + k0 + lseg * 8;
            const __nv_bfloat16* srcAl = AloR + (size_t)lrow * KDIM + k0 + lseg * 8;
            uint32_t doff0 = sw128((uint32_t)(lrow * 128 + lseg * 16));
            uint32_t doff1 = sw128((uint32_t)(lrow * 128 + (lseg + 1) * 16));
            uint32_t doff2 = sw128((uint32_t)(lrow * 128 + (lseg + 2) * 16));
            uint32_t doff3 = sw128((uint32_t)(lrow * 128 + (lseg + 3) * 16));
            CP_ASYNC16(base + doff0, srcAh);
            CP_ASYNC16(base + doff1, srcAh + 8);
            CP_ASYNC16(base + doff2, srcAh + 16);
            CP_ASYNC16(base + doff3, srcAh + 24);
            CP_ASYNC16(base + TILEB + doff0, srcAl);
            CP_ASYNC16(base + TILEB + doff1, srcAl + 8);
            CP_ASYNC16(base + TILEB + doff2, srcAl + 16);
            CP_ASYNC16(base + TILEB + doff3, srcAl + 24);
            if (!diag) {
                const __nv_bfloat16* srcBh = BhiR + (size_t)lrow * KDIM + k0 + lseg * 8;
                const __nv_bfloat16* srcBl = BloR + (size_t)lrow * KDIM + k0 + lseg * 8;
                CP_ASYNC16(base + 2 * TILEB + doff0, srcBh);
                CP_ASYNC16(base + 2 * TILEB + doff1, srcBh + 8);
                CP_ASYNC16(base + 2 * TILEB + doff2, srcBh + 16);
                CP_ASYNC16(base + 2 * TILEB + doff3, srcBh + 24);
                CP_ASYNC16(base + 3 * TILEB + doff0, srcBl);
                CP_ASYNC16(base + 3 * TILEB + doff1, srcBl + 8);
                CP_ASYNC16(base + 3 * TILEB + doff2, srcBl + 16);
                CP_ASYNC16(base + 3 * TILEB + doff3, srcBl + 24);
            }
        }
        CP_COMMIT();
    };

    load_chunk(0);
    load_chunk(1);

    for (int c = 0; c < n; c++) {
        CP_WAIT(1);
        __syncthreads();
        load_chunk(c + 2);

        uint32_t base = smb + (uint32_t)(c % NSTAGE) * BUFB;
        uint32_t ahiB = base, aloB = base + TILEB;
        uint32_t bhiB = diag ? base : base + 2 * TILEB;
        uint32_t bloB = diag ? base + TILEB : base + 3 * TILEB;
#pragma unroll
        for (int kk = 0; kk < 4; kk++) {
            uint32_t ah[4][4], al[4][4], bh[2][4], bl[2][4];
#pragma unroll
            for (int f = 0; f < 4; f++) {
                uint32_t o = sw128(arow[f] + kk * 32);
                LDSM4(ah[f], ahiB + o);
                LDSM4(al[f], aloB + o);
            }
#pragma unroll
            for (int g2 = 0; g2 < 2; g2++) {
                uint32_t o = sw128(brow[g2] + kk * 32);
                LDSM4(bh[g2], bhiB + o);
                LDSM4(bl[g2], bloB + o);
            }
#pragma unroll
            for (int f = 0; f < 4; f++)
#pragma unroll
                for (int g = 0; g < 4; g++) {
                    const uint32_t* Bh = &bh[g >> 1][(g & 1) * 2];
                    const uint32_t* Bl = &bl[g >> 1][(g & 1) * 2];
                    mma16816(acc[f][g], ah[f], Bh);
                    mma16816(acc[f][g], ah[f], Bl);
                    mma16816(acc[f][g], al[f], Bh);
                }
        }
        __syncthreads();
    }

#pragma unroll
    for (int f = 0; f < 4; f++)
#pragma unroll
        for (int g = 0; g < 4; g++) {
            int m = wr * 64 + f * 16 + (l >> 2);
            int nn = wc * 32 + g * 8 + (l & 3) * 2;
            int gm = ti * 128 + m, gn = tj * 128 + nn;
            *reinterpret_cast<float2*>(&g_part[s][b][gm][gn]) =
                make_float2(acc[f][g][0], acc[f][g][1]);
            *reinterpret_cast<float2*>(&g_part[s][b][gm + 8][gn]) =
                make_float2(acc[f][g][2], acc[f][g][3]);
        }
}

// ---------------- Kernel 2: deterministic split reduction + mirror ---------
__global__ void __launch_bounds__(256) reduce_kernel() {
    int gid = blockIdx.x * 256 + threadIdx.x;
    int b  = gid >> 16;
    int ij = gid & 65535;
    int i  = ij >> 8;
    int j  = ij & 255;
    int si = i, sj = j;
    if (i >= 128 && j < 128) { si = j; sj = i; }
    float acc = 0.0f;
#pragma unroll
    for (int s = 0; s < SPLITS; s++) acc += g_part[s][b][si][sj];
    g_G[b][i][j] = acc;
}

// ---------------- Kernel 3: farthest point sampling ----------------
__global__ void __launch_bounds__(256) fps_kernel(const float* __restrict__ pos) {
    int j = threadIdx.x;
    int mode = blockIdx.x;
    __shared__ double sdv[256];
    __shared__ int    sidx[256];
    __shared__ float  spx[256], spy[256], spz[256], snrm[256];
    __shared__ int    ssel[NKCLUST];

    const float* Gb = nullptr;
    if (mode == 0) {
        spx[j] = pos[j * 3 + 0]; spy[j] = pos[j * 3 + 1]; spz[j] = pos[j * 3 + 2];
    } else {
        Gb = &g_G[mode - 1][0][0];
    }
    __syncthreads();
    if (mode == 0) snrm[j] = spx[j] * spx[j] + spy[j] * spy[j] + spz[j] * spz[j];
    else           snrm[j] = Gb[j * 256 + j];
    __syncthreads();

    auto dist = [&](int i) -> float {
        float d2;
        if (mode == 0) {
            float dot = spx[i] * spx[j] + spy[i] * spy[j] + spz[i] * spz[j];
            d2 = snrm[i] + snrm[j] - 2.0f * dot;
        } else {
            d2 = snrm[i] + snrm[j] - 2.0f * Gb[i * 256 + j];
        }
        return sqrtf(fmaxf(d2, 0.0f));
    };

    double rs = 0.0;
    for (int i = 0; i < 256; i++) rs += (double)dist(i);
    sdv[j] = rs; sidx[j] = j;
    __syncthreads();
    for (int off = 128; off > 0; off >>= 1) {
        if (j < off) {
            double v2 = sdv[j + off]; int i2 = sidx[j + off];
            if (v2 > sdv[j] || (v2 == sdv[j] && i2 < sidx[j])) { sdv[j] = v2; sidx[j] = i2; }
        }
        __syncthreads();
    }
    int cur = sidx[0];
    __syncthreads();
    if (j == 0) ssel[0] = cur;
    float mind = dist(cur);

    for (int it = 1; it < NKCLUST; it++) {
        sdv[j] = (double)mind; sidx[j] = j;
        __syncthreads();
        for (int off = 128; off > 0; off >>= 1) {
            if (j < off) {
                double v2 = sdv[j + off]; int i2 = sidx[j + off];
                if (v2 > sdv[j] || (v2 == sdv[j] && i2 < sidx[j])) { sdv[j] = v2; sidx[j] = i2; }
            }
            __syncthreads();
        }
        cur = sidx[0];
        __syncthreads();
        if (j == 0) ssel[it] = cur;
        mind = fminf(mind, dist(cur));
    }
    __syncthreads();
    if (j < NKCLUST) {
        if (mode == 0) g_selpos[j] = ssel[j];
        else           g_sel[mode - 1][j] = ssel[j];
    }
}

// ---------------- Kernel 4: temp assignment ----------------
__global__ void __launch_bounds__(256) assign_kernel(const float* __restrict__ pos) {
    int b = blockIdx.x;
    int c = threadIdx.x;
    __shared__ float cx[NKCLUST], cy[NKCLUST], cz[NKCLUST], cn[NKCLUST];
    if (c < NKCLUST) {
        int si = g_sel[b][c];
        float x = pos[(b * 256 + si) * 3 + 0];
        float y = pos[(b * 256 + si) * 3 + 1];
        float z = pos[(b * 256 + si) * 3 + 2];
        cx[c] = x; cy[c] = y; cz[c] = z; cn[c] = x * x + y * y + z * z;
    }
    __syncthreads();
    float px = pos[(b * 256 + c) * 3 + 0];
    float py = pos[(b * 256 + c) * 3 + 1];
    float pz = pos[(b * 256 + c) * 3 + 2];
    float pn = px * px + py * py + pz * pz;
    float best = 1e30f; int bi = 0;
    for (int k = 0; k < NKCLUST; k++) {
        float d2 = pn + cn[k] - 2.0f * (px * cx[k] + py * cy[k] + pz * cz[k]);
        float d = sqrtf(fmaxf(d2, 0.0f));
        if (d < best) { best = d; bi = k; }
    }
    g_tassign[b][c] = bi;
}

// ---------------- Kernel 5: segment means + matching + update ----------------
__global__ void update_kernel(const float* __restrict__ pos) {
    int k = threadIdx.x;
    __shared__ float ax[NKCLUST], ay[NKCLUST], az[NKCLUST], an[NKCLUST];
    if (k < NKCLUST) {
        float sx = 0.f, sy = 0.f, sz = 0.f, cnt = 0.f;
        const int* ta = &g_tassign[0][0];
        for (int f = 0; f < NB * NC; f++) {
            if (ta[f] == k) {
                sx += pos[f * 3 + 0]; sy += pos[f * 3 + 1]; sz += pos[f * 3 + 2];
                cnt += 1.0f;
            }
        }
        if (cnt > 0.f) {
            float dn = fmaxf(cnt, 1.0f);
            ax[k] = sx / dn; ay[k] = sy / dn; az[k] = sz / dn;
        } else { ax[k] = 0.f; ay[k] = 0.f; az[k] = 0.f; }
        an[k] = ax[k] * ax[k] + ay[k] * ay[k] + az[k] * az[k];
    }
    __syncthreads();
    if (k < NKCLUST) {
        int si = g_selpos[k];
        float cx = pos[si * 3 + 0], cy = pos[si * 3 + 1], cz = pos[si * 3 + 2];
        float cnrm = cx * cx + cy * cy + cz * cz;
        float best = 1e30f; int bm = 0;
        for (int m = 0; m < NKCLUST; m++) {
            float d2 = cnrm + an[m] - 2.0f * (cx * ax[m] + cy * ay[m] + cz * az[m]);
            float d = sqrtf(fmaxf(d2, 0.0f));
            if (d < best) { best = d; bm = m; }
        }
        g_cent[k][0] = 0.8f * cx + 0.2f * ax[bm];
        g_cent[k][1] = 0.8f * cy + 0.2f * ay[bm];
        g_cent[k][2] = 0.8f * cz + 0.2f * az[bm];
    }
}

// ---------------- Kernel 6: stable argsort + greedy capacity assign ---------
__global__ void __launch_bounds__(256) final_kernel(const float* __restrict__ pos,
                                                    float* __restrict__ out) {
    int r = threadIdx.x;
    __shared__ float cx[NKCLUST], cy[NKCLUST], cz[NKCLUST], cn[NKCLUST];
    __shared__ unsigned char sord[256][NKCLUST];
    if (r < NKCLUST) {
        cx[r] = g_cent[r][0]; cy[r] = g_cent[r][1]; cz[r] = g_cent[r][2];
        cn[r] = cx[r] * cx[r] + cy[r] * cy[r] + cz[r] * cz[r];
    }
    __syncthreads();
    float px = pos[r * 3 + 0], py = pos[r * 3 + 1], pz = pos[r * 3 + 2];
    float pn = px * px + py * py + pz * pz;
    float d[NKCLUST];
    int ord[NKCLUST];
    for (int k = 0; k < NKCLUST; k++) {
        float d2 = pn + cn[k] - 2.0f * (px * cx[k] + py * cy[k] + pz * cz[k]);
        d[k] = sqrtf(fmaxf(d2, 0.0f));
        ord[k] = k;
    }
    for (int a = 1; a < NKCLUST; a++) {
        int key = ord[a]; float kd = d[key];
        int bq = a - 1;
        while (bq >= 0 && d[ord[bq]] > kd) { ord[bq + 1] = ord[bq]; bq--; }
        ord[bq + 1] = key;
    }
    for (int k = 0; k < NKCLUST; k++) sord[r][k] = (unsigned char)ord[k];
    __syncthreads();
    if (r == 0) {
        int counts[NKCLUST];
        for (int k = 0; k < NKCLUST; k++) counts[k] = 0;
        for (int rr = 0; rr < 256; rr++) {
            int chosen = sord[rr][0];
            for (int k = 0; k < NKCLUST; k++) {
                int cid = sord[rr][k];
                if (counts[cid] < 16) { chosen = cid; break; }
            }
            counts[chosen]++;
            out[rr] = (float)chosen;
        }
    }
}

// ---------------- launch ----------------
extern "C" void kernel_launch(void* const* d_in, const int* in_sizes, int n_in,
                              void* d_out, int out_size) {
    const float* features = nullptr;
    const float* pos = nullptr;
    for (int i = 0; i < n_in; i++) {
        if (in_sizes[i] == NB * NC * KDIM)   features = (const float*)d_in[i];
        else if (in_sizes[i] == NB * NC * 3) pos      = (const float*)d_in[i];
    }
    if (!features) features = (const float*)d_in[0];
    if (!pos)      pos      = (const float*)d_in[1];
    float* out = (float*)d_out;

    cudaFuncSetAttribute(gram_mma, cudaFuncAttributeMaxDynamicSharedMemorySize, SM_TOTAL);

    // slot-alignment: gram is the 4th launch (the ncu-profiled slot in R6/R8)
    dummy_kernel<<<1, 32>>>();
    dummy_kernel<<<1, 32>>>();
    convert_kernel<<<(NB * NC * KDIM) / (256 * 8), 256>>>(features);
    dim3 g1(3, SPLITS, NB);
    gram_mma<<<g1, 256, SM_TOTAL>>>(0);
    reduce_kernel<<<(NB * NC * NC) / 256, 256>>>();
    fps_kernel<<<9, 256>>>(pos);
    assign_kernel<<<NB, 256>>>(pos);
    update_kernel<<<1, 32>>>(pos);
    final_kernel<<<1, 256>>>(pos, out);
}

// round 11
// speedup vs baseline: 2.1194x; 1.2571x over previous
#include <cuda_runtime.h>
#include <cuda_bf16.h>
#include <cstdint>

#define KDIM 16384
#define NB 8
#define NC 256
#define NKCLUST 16
#define SPLITS 6
#define KC 64
#define TILEB 16384              // one 128x64 bf16 tile (128B rows)
#define BUFB  (4 * TILEB)        // Ahi,Alo,Bhi,Blo per stage
#define NSTAGE 3
#define SM_TOTAL (NSTAGE * BUFB) // 192KB dynamic smem
#define GT 512                   // gram threads (16 warps)

// ---------------- scratch ----------------
__device__ __nv_bfloat16 g_hi[NB][NC][KDIM];   // 67MB
__device__ __nv_bfloat16 g_lo[NB][NC][KDIM];   // 67MB
__device__ float  g_part[SPLITS][NB][NC][NC];
__device__ float  g_G[NB][NC][NC];
__device__ double g_rowpart[9][8][NC];
__device__ int    g_sel[NB][NKCLUST];
__device__ int    g_selpos[NKCLUST];
__device__ int    g_tassign[NB][NC];
__device__ float  g_cent[NKCLUST][3];

__device__ __forceinline__ uint32_t smem_u32(const void* p) {
    uint32_t a;
    asm("{ .reg .u64 t; cvta.to.shared.u64 t, %1; cvt.u32.u64 %0, t; }" : "=r"(a) : "l"(p));
    return a;
}
__device__ __forceinline__ uint32_t sw128(uint32_t off) { return off ^ ((off >> 3) & 0x70); }

#define CP_ASYNC16(dst, src) \
    asm volatile("cp.async.cg.shared.global [%0], [%1], 16;" :: "r"(dst), "l"(src))
#define CP_COMMIT() asm volatile("cp.async.commit_group;" ::: "memory")
#define CP_WAIT(N)  asm volatile("cp.async.wait_group %0;" :: "n"(N) : "memory")

#define LDSM4(r, addr) \
    asm volatile("ldmatrix.sync.aligned.m8n8.x4.shared.b16 {%0,%1,%2,%3}, [%4];" \
                 : "=r"((r)[0]), "=r"((r)[1]), "=r"((r)[2]), "=r"((r)[3]) : "r"(addr))

__device__ __forceinline__ void mma16816(float* c, const uint32_t* a, const uint32_t* b) {
    asm volatile("mma.sync.aligned.m16n8k16.row.col.f32.bf16.bf16.f32 "
                 "{%0,%1,%2,%3}, {%4,%5,%6,%7}, {%8,%9}, {%0,%1,%2,%3};"
                 : "+f"(c[0]), "+f"(c[1]), "+f"(c[2]), "+f"(c[3])
                 : "r"(a[0]), "r"(a[1]), "r"(a[2]), "r"(a[3]), "r"(b[0]), "r"(b[1]));
}

// ---------------- Kernel D: dummy (ncu slot alignment) ----------------
__global__ void dummy_kernel() {}

// ---------------- Kernel 0: fp32 -> bf16 hi/lo split (bandwidth pass) ------
__global__ void __launch_bounds__(256) convert_kernel(const float* __restrict__ A) {
    size_t gid = (size_t)blockIdx.x * 256 + threadIdx.x;
    size_t base = gid * 8;
    float4 v0 = *reinterpret_cast<const float4*>(A + base);
    float4 v1 = *reinterpret_cast<const float4*>(A + base + 4);
    __nv_bfloat162 h[4];
    h[0] = __float22bfloat162_rn(make_float2(v0.x, v0.y));
    h[1] = __float22bfloat162_rn(make_float2(v0.z, v0.w));
    h[2] = __float22bfloat162_rn(make_float2(v1.x, v1.y));
    h[3] = __float22bfloat162_rn(make_float2(v1.z, v1.w));
    float2 f0 = __bfloat1622float2(h[0]), f1 = __bfloat1622float2(h[1]);
    float2 f2 = __bfloat1622float2(h[2]), f3 = __bfloat1622float2(h[3]);
    __nv_bfloat162 l[4];
    l[0] = __float22bfloat162_rn(make_float2(v0.x - f0.x, v0.y - f0.y));
    l[1] = __float22bfloat162_rn(make_float2(v0.z - f1.x, v0.w - f1.y));
    l[2] = __float22bfloat162_rn(make_float2(v1.x - f2.x, v1.y - f2.y));
    l[3] = __float22bfloat162_rn(make_float2(v1.z - f3.x, v1.w - f3.y));
    *reinterpret_cast<uint4*>(&g_hi[0][0][0] + base) = *reinterpret_cast<uint4*>(h);
    *reinterpret_cast<uint4*>(&g_lo[0][0][0] + base) = *reinterpret_cast<uint4*>(l);
}

// ---------------- Kernel 1: bf16 mma.sync Gram, 16 warps, cp.async 3-stage -
// grid (3 tiles, SPLITS, NB), block 512. Warp grid 4x4, warp tile 32x32.
__global__ void __launch_bounds__(GT, 1) gram_mma(int unused) {
    extern __shared__ char smem[];
    uint32_t smb = smem_u32(smem);
    int tileId = blockIdx.x, s = blockIdx.y, b = blockIdx.z;
    int ti = (tileId == 2) ? 1 : 0;
    int tj = (tileId == 0) ? 0 : 1;
    bool diag = (ti == tj);

    const __nv_bfloat16* AhiR = &g_hi[b][ti * 128][0];
    const __nv_bfloat16* AloR = &g_lo[b][ti * 128][0];
    const __nv_bfloat16* BhiR = &g_hi[b][tj * 128][0];
    const __nv_bfloat16* BloR = &g_lo[b][tj * 128][0];

    int kb = ((s * KDIM) / SPLITS) & ~63;
    int ke = (((s + 1) * KDIM) / SPLITS) & ~63;
    if (s == SPLITS - 1) ke = KDIM;
    int n = (ke - kb) / KC;

    int t = threadIdx.x, l = t & 31, wid = t >> 5;
    int wr = wid >> 2, wc = wid & 3;        // 4x4 warp grid; warp tile 32x32

    int lrow = t >> 2;                      // 0..127, 4 threads per row
    int lseg = (t & 3) * 2;                 // 2 16B segs per thread per tile

    float acc[2][4][4];
#pragma unroll
    for (int f = 0; f < 2; f++)
#pragma unroll
        for (int g = 0; g < 4; g++)
#pragma unroll
            for (int q = 0; q < 4; q++) acc[f][g][q] = 0.0f;

    int mL = l & 15;
    int kaA = ((l >> 4) & 1) * 16;
    int nL = (l & 7) + ((l >> 4) & 1) * 8;
    int kaB = ((l >> 3) & 1) * 16;
    uint32_t arow[2], brow[2];
#pragma unroll
    for (int f = 0; f < 2; f++) arow[f] = (uint32_t)((wr * 32 + f * 16 + mL) * 128 + kaA);
#pragma unroll
    for (int g2 = 0; g2 < 2; g2++) brow[g2] = (uint32_t)((wc * 32 + g2 * 16 + nL) * 128 + kaB);

    auto load_chunk = [&](int c) {
        if (c < n) {
            int k0 = kb + c * KC;
            uint32_t base = smb + (uint32_t)(c % NSTAGE) * BUFB;
            const __nv_bfloat16* srcAh = AhiR + (size_t)lrow * KDIM + k0 + lseg * 8;
            const __nv_bfloat16* srcAl = AloR + (size_t)lrow * KDIM + k0 + lseg * 8;
            uint32_t doff0 = sw128((uint32_t)(lrow * 128 + lseg * 16));
            uint32_t doff1 = sw128((uint32_t)(lrow * 128 + (lseg + 1) * 16));
            CP_ASYNC16(base + doff0, srcAh);
            CP_ASYNC16(base + doff1, srcAh + 8);
            CP_ASYNC16(base + TILEB + doff0, srcAl);
            CP_ASYNC16(base + TILEB + doff1, srcAl + 8);
            if (!diag) {
                const __nv_bfloat16* srcBh = BhiR + (size_t)lrow * KDIM + k0 + lseg * 8;
                const __nv_bfloat16* srcBl = BloR + (size_t)lrow * KDIM + k0 + lseg * 8;
                CP_ASYNC16(base + 2 * TILEB + doff0, srcBh);
                CP_ASYNC16(base + 2 * TILEB + doff1, srcBh + 8);
                CP_ASYNC16(base + 3 * TILEB + doff0, srcBl);
                CP_ASYNC16(base + 3 * TILEB + doff1, srcBl + 8);
            }
        }
        CP_COMMIT();
    };

    load_chunk(0);
    load_chunk(1);

    for (int c = 0; c < n; c++) {
        CP_WAIT(1);
        __syncthreads();
        load_chunk(c + 2);

        uint32_t base = smb + (uint32_t)(c % NSTAGE) * BUFB;
        uint32_t ahiB = base, aloB = base + TILEB;
        uint32_t bhiB = diag ? base : base + 2 * TILEB;
        uint32_t bloB = diag ? base + TILEB : base + 3 * TILEB;
#pragma unroll
        for (int kk = 0; kk < 4; kk++) {
            uint32_t ah[2][4], al[2][4], bh[2][4], bl[2][4];
#pragma unroll
            for (int f = 0; f < 2; f++) {
                uint32_t o = sw128(arow[f] + kk * 32);
                LDSM4(ah[f], ahiB + o);
                LDSM4(al[f], aloB + o);
            }
#pragma unroll
            for (int g2 = 0; g2 < 2; g2++) {
                uint32_t o = sw128(brow[g2] + kk * 32);
                LDSM4(bh[g2], bhiB + o);
                LDSM4(bl[g2], bloB + o);
            }
#pragma unroll
            for (int f = 0; f < 2; f++)
#pragma unroll
                for (int g = 0; g < 4; g++) {
                    const uint32_t* Bh = &bh[g >> 1][(g & 1) * 2];
                    const uint32_t* Bl = &bl[g >> 1][(g & 1) * 2];
                    mma16816(acc[f][g], ah[f], Bh);
                    mma16816(acc[f][g], ah[f], Bl);
                    mma16816(acc[f][g], al[f], Bh);
                }
        }
        __syncthreads();
    }

#pragma unroll
    for (int f = 0; f < 2; f++)
#pragma unroll
        for (int g = 0; g < 4; g++) {
            int m = wr * 32 + f * 16 + (l >> 2);
            int nn = wc * 32 + g * 8 + (l & 3) * 2;
            int gm = ti * 128 + m, gn = tj * 128 + nn;
            *reinterpret_cast<float2*>(&g_part[s][b][gm][gn]) =
                make_float2(acc[f][g][0], acc[f][g][1]);
            *reinterpret_cast<float2*>(&g_part[s][b][gm + 8][gn]) =
                make_float2(acc[f][g][2], acc[f][g][3]);
        }
}

// ---------------- Kernel 2: deterministic split reduction + mirror ---------
__global__ void __launch_bounds__(256) reduce_kernel() {
    int gid = blockIdx.x * 256 + threadIdx.x;
    int b  = gid >> 16;
    int ij = gid & 65535;
    int i  = ij >> 8;
    int j  = ij & 255;
    int si = i, sj = j;
    if (i >= 128 && j < 128) { si = j; sj = i; }
    float acc = 0.0f;
#pragma unroll
    for (int s = 0; s < SPLITS; s++) acc += g_part[s][b][si][sj];
    g_G[b][i][j] = acc;
}

// ---------------- Kernel 2b: parallel row sums (hoisted from fps) ----------
// grid (9, 8) block 256: mode = bx, i-range = by*32..by*32+31; thread = j
__global__ void __launch_bounds__(256) rowsum_kernel(const float* __restrict__ pos) {
    int mode = blockIdx.x;
    int part = blockIdx.y;
    int j = threadIdx.x;
    double acc = 0.0;
    if (mode == 0) {
        float px = pos[j * 3 + 0], py = pos[j * 3 + 1], pz = pos[j * 3 + 2];
        float pn = px * px + py * py + pz * pz;
        for (int i = part * 32; i < part * 32 + 32; i++) {
            float qx = pos[i * 3 + 0], qy = pos[i * 3 + 1], qz = pos[i * 3 + 2];
            float qn = qx * qx + qy * qy + qz * qz;
            float d2 = qn + pn - 2.0f * (qx * px + qy * py + qz * pz);
            acc += (double)sqrtf(fmaxf(d2, 0.0f));
        }
    } else {
        const float* Gb = &g_G[mode - 1][0][0];
        float nj = Gb[j * 256 + j];
        for (int i = part * 32; i < part * 32 + 32; i++) {
            float d2 = Gb[i * 256 + i] + nj - 2.0f * Gb[i * 256 + j];
            acc += (double)sqrtf(fmaxf(d2, 0.0f));
        }
    }
    g_rowpart[mode][part][j] = acc;
}

// ---------------- Kernel 3: farthest point sampling ----------------
__global__ void __launch_bounds__(256) fps_kernel(const float* __restrict__ pos) {
    int j = threadIdx.x;
    int mode = blockIdx.x;
    __shared__ double sdv[256];
    __shared__ int    sidx[256];
    __shared__ float  spx[256], spy[256], spz[256], snrm[256];
    __shared__ int    ssel[NKCLUST];

    const float* Gb = nullptr;
    if (mode == 0) {
        spx[j] = pos[j * 3 + 0]; spy[j] = pos[j * 3 + 1]; spz[j] = pos[j * 3 + 2];
    } else {
        Gb = &g_G[mode - 1][0][0];
    }
    __syncthreads();
    if (mode == 0) snrm[j] = spx[j] * spx[j] + spy[j] * spy[j] + spz[j] * spz[j];
    else           snrm[j] = Gb[j * 256 + j];
    __syncthreads();

    auto dist = [&](int i) -> float {
        float d2;
        if (mode == 0) {
            float dot = spx[i] * spx[j] + spy[i] * spy[j] + spz[i] * spz[j];
            d2 = snrm[i] + snrm[j] - 2.0f * dot;
        } else {
            d2 = snrm[i] + snrm[j] - 2.0f * Gb[i * 256 + j];
        }
        return sqrtf(fmaxf(d2, 0.0f));
    };

    // start = argmax of row sums (precomputed partials, fixed combine order)
    double rs = 0.0;
#pragma unroll
    for (int p = 0; p < 8; p++) rs += g_rowpart[mode][p][j];
    sdv[j] = rs; sidx[j] = j;
    __syncthreads();
    for (int off = 128; off > 0; off >>= 1) {
        if (j < off) {
            double v2 = sdv[j + off]; int i2 = sidx[j + off];
            if (v2 > sdv[j] || (v2 == sdv[j] && i2 < sidx[j])) { sdv[j] = v2; sidx[j] = i2; }
        }
        __syncthreads();
    }
    int cur = sidx[0];
    __syncthreads();
    if (j == 0) ssel[0] = cur;
    float mind = dist(cur);

    for (int it = 1; it < NKCLUST; it++) {
        sdv[j] = (double)mind; sidx[j] = j;
        __syncthreads();
        for (int off = 128; off > 0; off >>= 1) {
            if (j < off) {
                double v2 = sdv[j + off]; int i2 = sidx[j + off];
                if (v2 > sdv[j] || (v2 == sdv[j] && i2 < sidx[j])) { sdv[j] = v2; sidx[j] = i2; }
            }
            __syncthreads();
        }
        cur = sidx[0];
        __syncthreads();
        if (j == 0) ssel[it] = cur;
        mind = fminf(mind, dist(cur));
    }
    __syncthreads();
    if (j < NKCLUST) {
        if (mode == 0) g_selpos[j] = ssel[j];
        else           g_sel[mode - 1][j] = ssel[j];
    }
}

// ---------------- Kernel 4: temp assignment ----------------
__global__ void __launch_bounds__(256) assign_kernel(const float* __restrict__ pos) {
    int b = blockIdx.x;
    int c = threadIdx.x;
    __shared__ float cx[NKCLUST], cy[NKCLUST], cz[NKCLUST], cn[NKCLUST];
    if (c < NKCLUST) {
        int si = g_sel[b][c];
        float x = pos[(b * 256 + si) * 3 + 0];
        float y = pos[(b * 256 + si) * 3 + 1];
        float z = pos[(b * 256 + si) * 3 + 2];
        cx[c] = x; cy[c] = y; cz[c] = z; cn[c] = x * x + y * y + z * z;
    }
    __syncthreads();
    float px = pos[(b * 256 + c) * 3 + 0];
    float py = pos[(b * 256 + c) * 3 + 1];
    float pz = pos[(b * 256 + c) * 3 + 2];
    float pn = px * px + py * py + pz * pz;
    float best = 1e30f; int bi = 0;
    for (int k = 0; k < NKCLUST; k++) {
        float d2 = pn + cn[k] - 2.0f * (px * cx[k] + py * cy[k] + pz * cz[k]);
        float d = sqrtf(fmaxf(d2, 0.0f));
        if (d < best) { best = d; bi = k; }
    }
    g_tassign[b][c] = bi;
}

// ---------------- Kernel 5: segment means + matching + update ----------------
__global__ void update_kernel(const float* __restrict__ pos) {
    int k = threadIdx.x;
    __shared__ float ax[NKCLUST], ay[NKCLUST], az[NKCLUST], an[NKCLUST];
    if (k < NKCLUST) {
        float sx = 0.f, sy = 0.f, sz = 0.f, cnt = 0.f;
        const int* ta = &g_tassign[0][0];
        for (int f = 0; f < NB * NC; f++) {
            if (ta[f] == k) {
                sx += pos[f * 3 + 0]; sy += pos[f * 3 + 1]; sz += pos[f * 3 + 2];
                cnt += 1.0f;
            }
        }
        if (cnt > 0.f) {
            float dn = fmaxf(cnt, 1.0f);
            ax[k] = sx / dn; ay[k] = sy / dn; az[k] = sz / dn;
        } else { ax[k] = 0.f; ay[k] = 0.f; az[k] = 0.f; }
        an[k] = ax[k] * ax[k] + ay[k] * ay[k] + az[k] * az[k];
    }
    __syncthreads();
    if (k < NKCLUST) {
        int si = g_selpos[k];
        float cx = pos[si * 3 + 0], cy = pos[si * 3 + 1], cz = pos[si * 3 + 2];
        float cnrm = cx * cx + cy * cy + cz * cz;
        float best = 1e30f; int bm = 0;
        for (int m = 0; m < NKCLUST; m++) {
            float d2 = cnrm + an[m] - 2.0f * (cx * ax[m] + cy * ay[m] + cz * az[m]);
            float d = sqrtf(fmaxf(d2, 0.0f));
            if (d < best) { best = d; bm = m; }
        }
        g_cent[k][0] = 0.8f * cx + 0.2f * ax[bm];
        g_cent[k][1] = 0.8f * cy + 0.2f * ay[bm];
        g_cent[k][2] = 0.8f * cz + 0.2f * az[bm];
    }
}

// ---------------- Kernel 6: stable argsort + greedy capacity assign ---------
__global__ void __launch_bounds__(256) final_kernel(const float* __restrict__ pos,
                                                    float* __restrict__ out) {
    int r = threadIdx.x;
    __shared__ float cx[NKCLUST], cy[NKCLUST], cz[NKCLUST], cn[NKCLUST];
    __shared__ unsigned char sord[256][NKCLUST];
    __shared__ int scounts[NKCLUST];
    if (r < NKCLUST) {
        cx[r] = g_cent[r][0]; cy[r] = g_cent[r][1]; cz[r] = g_cent[r][2];
        cn[r] = cx[r] * cx[r] + cy[r] * cy[r] + cz[r] * cz[r];
        scounts[r] = 0;
    }
    __syncthreads();
    float px = pos[r * 3 + 0], py = pos[r * 3 + 1], pz = pos[r * 3 + 2];
    float pn = px * px + py * py + pz * pz;
    float d[NKCLUST];
    int ord[NKCLUST];
    for (int k = 0; k < NKCLUST; k++) {
        float d2 = pn + cn[k] - 2.0f * (px * cx[k] + py * cy[k] + pz * cz[k]);
        d[k] = sqrtf(fmaxf(d2, 0.0f));
        ord[k] = k;
    }
    for (int a = 1; a < NKCLUST; a++) {
        int key = ord[a]; float kd = d[key];
        int bq = a - 1;
        while (bq >= 0 && d[ord[bq]] > kd) { ord[bq + 1] = ord[bq]; bq--; }
        ord[bq + 1] = key;
    }
    for (int k = 0; k < NKCLUST; k++) sord[r][k] = (unsigned char)ord[k];
    __syncthreads();
    if (r == 0) {
        for (int rr = 0; rr < 256; rr++) {
            int chosen = sord[rr][0];
            for (int k = 0; k < NKCLUST; k++) {
                int cid = sord[rr][k];
                if (scounts[cid] < 16) { chosen = cid; break; }
            }
            scounts[chosen]++;
            out[rr] = (float)chosen;
        }
    }
}

// ---------------- launch ----------------
extern "C" void kernel_launch(void* const* d_in, const int* in_sizes, int n_in,
                              void* d_out, int out_size) {
    const float* features = nullptr;
    const float* pos = nullptr;
    for (int i = 0; i < n_in; i++) {
        if (in_sizes[i] == NB * NC * KDIM)   features = (const float*)d_in[i];
        else if (in_sizes[i] == NB * NC * 3) pos      = (const float*)d_in[i];
    }
    if (!features) features = (const float*)d_in[0];
    if (!pos)      pos      = (const float*)d_in[1];
    float* out = (float*)d_out;

    cudaFuncSetAttribute(gram_mma, cudaFuncAttributeMaxDynamicSharedMemorySize, SM_TOTAL);

    // slot-alignment: gram stays the 4th launch (ncu-profiled slot)
    dummy_kernel<<<1, 32>>>();
    dummy_kernel<<<1, 32>>>();
    convert_kernel<<<(NB * NC * KDIM) / (256 * 8), 256>>>(features);
    dim3 g1(3, SPLITS, NB);
    gram_mma<<<g1, GT, SM_TOTAL>>>(0);
    reduce_kernel<<<(NB * NC * NC) / 256, 256>>>();
    dim3 g2(9, 8);
    rowsum_kernel<<<g2, 256>>>(pos);
    fps_kernel<<<9, 256>>>(pos);
    assign_kernel<<<NB, 256>>>(pos);
    update_kernel<<<1, 32>>>(pos);
    final_kernel<<<1, 256>>>(pos, out);
}

// round 12
// speedup vs baseline: 2.6565x; 1.2535x over previous
#include <cuda_runtime.h>
#include <cuda_bf16.h>
#include <cstdint>

#define KDIM 16384
#define NB 8
#define NC 256
#define NKCLUST 16
#define SPLITS 12
#define KC 32
#define TILEB 8192               // one 128x32 bf16 tile (64B rows)
#define BUFB  (4 * TILEB)        // Ahi,Alo,Bhi,Blo per stage = 32KB
#define NSTAGE 3
#define SM_TOTAL (NSTAGE * BUFB) // 96KB dynamic smem -> 2 CTAs/SM
#define GT 256

// ---------------- scratch ----------------
__device__ __nv_bfloat16 g_hi[NB][NC][KDIM];
__device__ __nv_bfloat16 g_lo[NB][NC][KDIM];
__device__ float  g_part[SPLITS][NB][NC][NC];
__device__ float  g_G[NB][NC][NC];
__device__ double g_rowpart[9][8][NC];
__device__ int    g_sel[NB][NKCLUST];
__device__ int    g_selpos[NKCLUST];
__device__ float  g_cent[NKCLUST][3];

__device__ __forceinline__ uint32_t smem_u32(const void* p) {
    uint32_t a;
    asm("{ .reg .u64 t; cvta.to.shared.u64 t, %1; cvt.u32.u64 %0, t; }" : "=r"(a) : "l"(p));
    return a;
}
__device__ __forceinline__ uint32_t sw64(uint32_t off) { return off ^ ((off >> 3) & 0x30); }

#define CP_ASYNC16(dst, src) \
    asm volatile("cp.async.cg.shared.global [%0], [%1], 16;" :: "r"(dst), "l"(src))
#define CP_COMMIT() asm volatile("cp.async.commit_group;" ::: "memory")
#define CP_WAIT(N)  asm volatile("cp.async.wait_group %0;" :: "n"(N) : "memory")

#define LDSM4(r, addr) \
    asm volatile("ldmatrix.sync.aligned.m8n8.x4.shared.b16 {%0,%1,%2,%3}, [%4];" \
                 : "=r"((r)[0]), "=r"((r)[1]), "=r"((r)[2]), "=r"((r)[3]) : "r"(addr))

__device__ __forceinline__ void mma16816(float* c, const uint32_t* a, const uint32_t* b) {
    asm volatile("mma.sync.aligned.m16n8k16.row.col.f32.bf16.bf16.f32 "
                 "{%0,%1,%2,%3}, {%4,%5,%6,%7}, {%8,%9}, {%0,%1,%2,%3};"
                 : "+f"(c[0]), "+f"(c[1]), "+f"(c[2]), "+f"(c[3])
                 : "r"(a[0]), "r"(a[1]), "r"(a[2]), "r"(a[3]), "r"(b[0]), "r"(b[1]));
}

// ---------------- Kernel D: dummy (ncu slot alignment) ----------------
__global__ void dummy_kernel() {}

// ---------------- Kernel 0: fp32 -> bf16 hi/lo split ----------------
__global__ void __launch_bounds__(256) convert_kernel(const float* __restrict__ A) {
    size_t gid = (size_t)blockIdx.x * 256 + threadIdx.x;
    size_t base = gid * 8;
    float4 v0 = *reinterpret_cast<const float4*>(A + base);
    float4 v1 = *reinterpret_cast<const float4*>(A + base + 4);
    __nv_bfloat162 h[4];
    h[0] = __float22bfloat162_rn(make_float2(v0.x, v0.y));
    h[1] = __float22bfloat162_rn(make_float2(v0.z, v0.w));
    h[2] = __float22bfloat162_rn(make_float2(v1.x, v1.y));
    h[3] = __float22bfloat162_rn(make_float2(v1.z, v1.w));
    float2 f0 = __bfloat1622float2(h[0]), f1 = __bfloat1622float2(h[1]);
    float2 f2 = __bfloat1622float2(h[2]), f3 = __bfloat1622float2(h[3]);
    __nv_bfloat162 l[4];
    l[0] = __float22bfloat162_rn(make_float2(v0.x - f0.x, v0.y - f0.y));
    l[1] = __float22bfloat162_rn(make_float2(v0.z - f1.x, v0.w - f1.y));
    l[2] = __float22bfloat162_rn(make_float2(v1.x - f2.x, v1.y - f2.y));
    l[3] = __float22bfloat162_rn(make_float2(v1.z - f3.x, v1.w - f3.y));
    *reinterpret_cast<uint4*>(&g_hi[0][0][0] + base) = *reinterpret_cast<uint4*>(h);
    *reinterpret_cast<uint4*>(&g_lo[0][0][0] + base) = *reinterpret_cast<uint4*>(l);
}

// ---------------- Kernel 1: bf16 mma.sync Gram, 2 CTAs/SM, KC=32 ----------
// grid (3 tiles, SPLITS, NB), block 256. Warp grid 2x4, warp tile 64x32.
__global__ void __launch_bounds__(GT, 2) gram_mma(int unused) {
    extern __shared__ char smem[];
    uint32_t smb = smem_u32(smem);
    int tileId = blockIdx.x, s = blockIdx.y, b = blockIdx.z;
    int ti = (tileId == 2) ? 1 : 0;
    int tj = (tileId == 0) ? 0 : 1;
    bool diag = (ti == tj);

    const __nv_bfloat16* AhiR = &g_hi[b][ti * 128][0];
    const __nv_bfloat16* AloR = &g_lo[b][ti * 128][0];
    const __nv_bfloat16* BhiR = &g_hi[b][tj * 128][0];
    const __nv_bfloat16* BloR = &g_lo[b][tj * 128][0];

    int kb = ((s * KDIM) / SPLITS) & ~31;
    int ke = (((s + 1) * KDIM) / SPLITS) & ~31;
    if (s == SPLITS - 1) ke = KDIM;
    int n = (ke - kb) / KC;

    int t = threadIdx.x, l = t & 31, wid = t >> 5;
    int wr = wid >> 2, wc = wid & 3;        // 2x4 warp grid; warp tile 64x32

    int lrow = t >> 1;                      // 0..127
    int lseg = (t & 1) * 2;                 // 2 16B segs/thread/tile (4 segs/row)

    float acc[4][4][4];
#pragma unroll
    for (int f = 0; f < 4; f++)
#pragma unroll
        for (int g = 0; g < 4; g++)
#pragma unroll
            for (int q = 0; q < 4; q++) acc[f][g][q] = 0.0f;

    int mL = l & 15;
    int kaA = ((l >> 4) & 1) * 16;
    int nL = (l & 7) + ((l >> 4) & 1) * 8;
    int kaB = ((l >> 3) & 1) * 16;
    uint32_t arow[4], brow[2];
#pragma unroll
    for (int f = 0; f < 4; f++) arow[f] = (uint32_t)((wr * 64 + f * 16 + mL) * 64 + kaA);
#pragma unroll
    for (int g2 = 0; g2 < 2; g2++) brow[g2] = (uint32_t)((wc * 32 + g2 * 16 + nL) * 64 + kaB);

    auto load_chunk = [&](int c) {
        if (c < n) {
            int k0 = kb + c * KC;
            uint32_t base = smb + (uint32_t)(c % NSTAGE) * BUFB;
            const __nv_bfloat16* srcAh = AhiR + (size_t)lrow * KDIM + k0 + lseg * 8;
            const __nv_bfloat16* srcAl = AloR + (size_t)lrow * KDIM + k0 + lseg * 8;
            uint32_t doff0 = sw64((uint32_t)(lrow * 64 + lseg * 16));
            uint32_t doff1 = sw64((uint32_t)(lrow * 64 + (lseg + 1) * 16));
            CP_ASYNC16(base + doff0, srcAh);
            CP_ASYNC16(base + doff1, srcAh + 8);
            CP_ASYNC16(base + TILEB + doff0, srcAl);
            CP_ASYNC16(base + TILEB + doff1, srcAl + 8);
            if (!diag) {
                const __nv_bfloat16* srcBh = BhiR + (size_t)lrow * KDIM + k0 + lseg * 8;
                const __nv_bfloat16* srcBl = BloR + (size_t)lrow * KDIM + k0 + lseg * 8;
                CP_ASYNC16(base + 2 * TILEB + doff0, srcBh);
                CP_ASYNC16(base + 2 * TILEB + doff1, srcBh + 8);
                CP_ASYNC16(base + 3 * TILEB + doff0, srcBl);
                CP_ASYNC16(base + 3 * TILEB + doff1, srcBl + 8);
            }
        }
        CP_COMMIT();
    };

    load_chunk(0);
    load_chunk(1);

    for (int c = 0; c < n; c++) {
        CP_WAIT(1);
        __syncthreads();
        load_chunk(c + 2);

        uint32_t base = smb + (uint32_t)(c % NSTAGE) * BUFB;
        uint32_t ahiB = base, aloB = base + TILEB;
        uint32_t bhiB = diag ? base : base + 2 * TILEB;
        uint32_t bloB = diag ? base + TILEB : base + 3 * TILEB;
#pragma unroll
        for (int kk = 0; kk < 2; kk++) {
            uint32_t bh[2][4], bl[2][4];
#pragma unroll
            for (int g2 = 0; g2 < 2; g2++) {
                uint32_t o = sw64(brow[g2] + kk * 32);
                LDSM4(bh[g2], bhiB + o);
                LDSM4(bl[g2], bloB + o);
            }
#pragma unroll
            for (int f = 0; f < 4; f++) {
                uint32_t ah[4], al[4];
                uint32_t o = sw64(arow[f] + kk * 32);
                LDSM4(ah, ahiB + o);
                LDSM4(al, aloB + o);
#pragma unroll
                for (int g = 0; g < 4; g++) {
                    const uint32_t* Bh = &bh[g >> 1][(g & 1) * 2];
                    const uint32_t* Bl = &bl[g >> 1][(g & 1) * 2];
                    mma16816(acc[f][g], ah, Bh);
                    mma16816(acc[f][g], ah, Bl);
                    mma16816(acc[f][g], al, Bh);
                }
            }
        }
        __syncthreads();
    }

#pragma unroll
    for (int f = 0; f < 4; f++)
#pragma unroll
        for (int g = 0; g < 4; g++) {
            int m = wr * 64 + f * 16 + (l >> 2);
            int nn = wc * 32 + g * 8 + (l & 3) * 2;
            int gm = ti * 128 + m, gn = tj * 128 + nn;
            *reinterpret_cast<float2*>(&g_part[s][b][gm][gn]) =
                make_float2(acc[f][g][0], acc[f][g][1]);
            *reinterpret_cast<float2*>(&g_part[s][b][gm + 8][gn]) =
                make_float2(acc[f][g][2], acc[f][g][3]);
        }
}

// ---------------- Kernel 2: deterministic split reduction + mirror ---------
__global__ void __launch_bounds__(256) reduce_kernel() {
    int gid = blockIdx.x * 256 + threadIdx.x;
    int b  = gid >> 16;
    int ij = gid & 65535;
    int i  = ij >> 8;
    int j  = ij & 255;
    int si = i, sj = j;
    if (i >= 128 && j < 128) { si = j; sj = i; }
    float acc = 0.0f;
#pragma unroll
    for (int s = 0; s < SPLITS; s++) acc += g_part[s][b][si][sj];
    g_G[b][i][j] = acc;
}

// ---------------- Kernel 2b: parallel row sums ----------------
__global__ void __launch_bounds__(256) rowsum_kernel(const float* __restrict__ pos) {
    int mode = blockIdx.x;
    int part = blockIdx.y;
    int j = threadIdx.x;
    double acc = 0.0;
    if (mode == 0) {
        float px = pos[j * 3 + 0], py = pos[j * 3 + 1], pz = pos[j * 3 + 2];
        float pn = px * px + py * py + pz * pz;
        for (int i = part * 32; i < part * 32 + 32; i++) {
            float qx = pos[i * 3 + 0], qy = pos[i * 3 + 1], qz = pos[i * 3 + 2];
            float qn = qx * qx + qy * qy + qz * qz;
            float d2 = qn + pn - 2.0f * (qx * px + qy * py + qz * pz);
            acc += (double)sqrtf(fmaxf(d2, 0.0f));
        }
    } else {
        const float* Gb = &g_G[mode - 1][0][0];
        float nj = Gb[j * 256 + j];
        for (int i = part * 32; i < part * 32 + 32; i++) {
            float d2 = Gb[i * 256 + i] + nj - 2.0f * Gb[i * 256 + j];
            acc += (double)sqrtf(fmaxf(d2, 0.0f));
        }
    }
    g_rowpart[mode][part][j] = acc;
}

// ---------------- Kernel 3: farthest point sampling ----------------
__global__ void __launch_bounds__(256) fps_kernel(const float* __restrict__ pos) {
    int j = threadIdx.x;
    int mode = blockIdx.x;
    __shared__ double sdv[256];
    __shared__ int    sidx[256];
    __shared__ float  spx[256], spy[256], spz[256], snrm[256];
    __shared__ int    ssel[NKCLUST];

    const float* Gb = nullptr;
    if (mode == 0) {
        spx[j] = pos[j * 3 + 0]; spy[j] = pos[j * 3 + 1]; spz[j] = pos[j * 3 + 2];
    } else {
        Gb = &g_G[mode - 1][0][0];
    }
    __syncthreads();
    if (mode == 0) snrm[j] = spx[j] * spx[j] + spy[j] * spy[j] + spz[j] * spz[j];
    else           snrm[j] = Gb[j * 256 + j];
    __syncthreads();

    auto dist = [&](int i) -> float {
        float d2;
        if (mode == 0) {
            float dot = spx[i] * spx[j] + spy[i] * spy[j] + spz[i] * spz[j];
            d2 = snrm[i] + snrm[j] - 2.0f * dot;
        } else {
            d2 = snrm[i] + snrm[j] - 2.0f * Gb[i * 256 + j];
        }
        return sqrtf(fmaxf(d2, 0.0f));
    };

    double rs = 0.0;
#pragma unroll
    for (int p = 0; p < 8; p++) rs += g_rowpart[mode][p][j];
    sdv[j] = rs; sidx[j] = j;
    __syncthreads();
    for (int off = 128; off > 0; off >>= 1) {
        if (j < off) {
            double v2 = sdv[j + off]; int i2 = sidx[j + off];
            if (v2 > sdv[j] || (v2 == sdv[j] && i2 < sidx[j])) { sdv[j] = v2; sidx[j] = i2; }
        }
        __syncthreads();
    }
    int cur = sidx[0];
    __syncthreads();
    if (j == 0) ssel[0] = cur;
    float mind = dist(cur);

    for (int it = 1; it < NKCLUST; it++) {
        sdv[j] = (double)mind; sidx[j] = j;
        __syncthreads();
        for (int off = 128; off > 0; off >>= 1) {
            if (j < off) {
                double v2 = sdv[j + off]; int i2 = sidx[j + off];
                if (v2 > sdv[j] || (v2 == sdv[j] && i2 < sidx[j])) { sdv[j] = v2; sidx[j] = i2; }
            }
            __syncthreads();
        }
        cur = sidx[0];
        __syncthreads();
        if (j == 0) ssel[it] = cur;
        mind = fminf(mind, dist(cur));
    }
    __syncthreads();
    if (j < NKCLUST) {
        if (mode == 0) g_selpos[j] = ssel[j];
        else           g_sel[mode - 1][j] = ssel[j];
    }
}

// ---------------- Kernel 4: fused assign + update + final ----------------
__global__ void __launch_bounds__(512) tail_kernel(const float* __restrict__ pos,
                                                   float* __restrict__ out) {
    __shared__ float spos[NB * NC * 3];          // 24KB
    __shared__ float scx[NB][NKCLUST], scy[NB][NKCLUST], scz[NB][NKCLUST], scn[NB][NKCLUST];
    __shared__ int   sta[NB * NC];               // 8KB
    __shared__ float ax[NKCLUST], ay[NKCLUST], az[NKCLUST], an[NKCLUST];
    __shared__ float fcx[NKCLUST], fcy[NKCLUST], fcz[NKCLUST], fcn[NKCLUST];
    __shared__ unsigned char sord[256][NKCLUST]; // 4KB
    __shared__ int scounts[NKCLUST];

    int t = threadIdx.x;
    for (int i = t; i < NB * NC * 3; i += 512) spos[i] = pos[i];
    if (t < NKCLUST) scounts[t] = 0;
    __syncthreads();

    // per-batch centers from fps selections
    if (t < NB * NKCLUST) {
        int b = t >> 4, k = t & 15;
        int si = g_sel[b][k];
        float x = spos[(b * 256 + si) * 3 + 0];
        float y = spos[(b * 256 + si) * 3 + 1];
        float z = spos[(b * 256 + si) * 3 + 2];
        scx[b][k] = x; scy[b][k] = y; scz[b][k] = z; scn[b][k] = x * x + y * y + z * z;
    }
    __syncthreads();

    // temp assignment: 4 points per thread
    for (int p = t; p < NB * NC; p += 512) {
        int b = p >> 8;
        float px = spos[p * 3 + 0], py = spos[p * 3 + 1], pz = spos[p * 3 + 2];
        float pn = px * px + py * py + pz * pz;
        float best = 1e30f; int bi = 0;
        for (int k = 0; k < NKCLUST; k++) {
            float d2 = pn + scn[b][k] - 2.0f * (px * scx[b][k] + py * scy[b][k] + pz * scz[b][k]);
            float d = sqrtf(fmaxf(d2, 0.0f));
            if (d < best) { best = d; bi = k; }
        }
        sta[p] = bi;
    }
    __syncthreads();

    // segment means: warp w handles cluster w
    int wid = t >> 5, l = t & 31;
    if (wid < NKCLUST) {
        float sx = 0.f, sy = 0.f, sz = 0.f, cnt = 0.f;
        for (int p = l; p < NB * NC; p += 32) {
            if (sta[p] == wid) {
                sx += spos[p * 3 + 0]; sy += spos[p * 3 + 1]; sz += spos[p * 3 + 2];
                cnt += 1.0f;
            }
        }
#pragma unroll
        for (int off = 16; off > 0; off >>= 1) {
            sx  += __shfl_down_sync(0xffffffffu, sx,  off);
            sy  += __shfl_down_sync(0xffffffffu, sy,  off);
            sz  += __shfl_down_sync(0xffffffffu, sz,  off);
            cnt += __shfl_down_sync(0xffffffffu, cnt, off);
        }
        if (l == 0) {
            if (cnt > 0.f) {
                float dn = fmaxf(cnt, 1.0f);
                ax[wid] = sx / dn; ay[wid] = sy / dn; az[wid] = sz / dn;
            } else { ax[wid] = 0.f; ay[wid] = 0.f; az[wid] = 0.f; }
            an[wid] = ax[wid] * ax[wid] + ay[wid] * ay[wid] + az[wid] * az[wid];
        }
    }
    __syncthreads();

    // matching + center update
    if (t < NKCLUST) {
        int si = g_selpos[t];
        float cx = spos[si * 3 + 0], cy = spos[si * 3 + 1], cz = spos[si * 3 + 2];
        float cnrm = cx * cx + cy * cy + cz * cz;
        float best = 1e30f; int bm = 0;
        for (int m = 0; m < NKCLUST; m++) {
            float d2 = cnrm + an[m] - 2.0f * (cx * ax[m] + cy * ay[m] + cz * az[m]);
            float d = sqrtf(fmaxf(d2, 0.0f));
            if (d < best) { best = d; bm = m; }
        }
        float nx = 0.8f * cx + 0.2f * ax[bm];
        float ny = 0.8f * cy + 0.2f * ay[bm];
        float nz = 0.8f * cz + 0.2f * az[bm];
        fcx[t] = nx; fcy[t] = ny; fcz[t] = nz; fcn[t] = nx * nx + ny * ny + nz * nz;
    }
    __syncthreads();

    // stable argsort of distances to final centers
    if (t < 256) {
        float px = spos[t * 3 + 0], py = spos[t * 3 + 1], pz = spos[t * 3 + 2];
        float pn = px * px + py * py + pz * pz;
        float d[NKCLUST];
        int ord[NKCLUST];
        for (int k = 0; k < NKCLUST; k++) {
            float d2 = pn + fcn[k] - 2.0f * (px * fcx[k] + py * fcy[k] + pz * fcz[k]);
            d[k] = sqrtf(fmaxf(d2, 0.0f));
            ord[k] = k;
        }
        for (int a = 1; a < NKCLUST; a++) {
            int key = ord[a]; float kd = d[key];
            int bq = a - 1;
            while (bq >= 0 && d[ord[bq]] > kd) { ord[bq + 1] = ord[bq]; bq--; }
            ord[bq + 1] = key;
        }
        for (int k = 0; k < NKCLUST; k++) sord[t][k] = (unsigned char)ord[k];
    }
    __syncthreads();

    // greedy capacity assign (serial, thread 0)
    if (t == 0) {
        for (int rr = 0; rr < 256; rr++) {
            int chosen = sord[rr][0];
            for (int k = 0; k < NKCLUST; k++) {
                int cid = sord[rr][k];
                if (scounts[cid] < 16) { chosen = cid; break; }
            }
            scounts[chosen]++;
            out[rr] = (float)chosen;
        }
    }
}

// ---------------- launch ----------------
extern "C" void kernel_launch(void* const* d_in, const int* in_sizes, int n_in,
                              void* d_out, int out_size) {
    const float* features = nullptr;
    const float* pos = nullptr;
    for (int i = 0; i < n_in; i++) {
        if (in_sizes[i] == NB * NC * KDIM)   features = (const float*)d_in[i];
        else if (in_sizes[i] == NB * NC * 3) pos      = (const float*)d_in[i];
    }
    if (!features) features = (const float*)d_in[0];
    if (!pos)      pos      = (const float*)d_in[1];
    float* out = (float*)d_out;

    cudaFuncSetAttribute(gram_mma, cudaFuncAttributeMaxDynamicSharedMemorySize, SM_TOTAL);

    // slot-alignment: gram stays the 4th launch (ncu-profiled slot)
    dummy_kernel<<<1, 32>>>();
    dummy_kernel<<<1, 32>>>();
    convert_kernel<<<(NB * NC * KDIM) / (256 * 8), 256>>>(features);
    dim3 g1(3, SPLITS, NB);
    gram_mma<<<g1, GT, SM_TOTAL>>>(0);
    reduce_kernel<<<(NB * NC * NC) / 256, 256>>>();
    dim3 g2(9, 8);
    rowsum_kernel<<<g2, 256>>>(pos);
    fps_kernel<<<9, 256>>>(pos);
    tail_kernel<<<1, 512>>>(pos, out);
}